// round 2
// baseline (speedup 1.0000x reference)
#include <cuda_runtime.h>
#include <cuda_bf16.h>

#define BATCH 256
#define NV 10475
#define NJ 55
#define PB 486            // pose basis = 54*9
#define NC3 (NV*3)        // 31425
#define JOFF (BATCH*NC3)  // offset of joints in d_out

// ---- scratch (device globals; no allocation allowed) ----
#define CHUNK 96
#define NCH 110           // ceil(10475/96)
__device__ float g_jr_partial[NCH * 3465];
__device__ float g_jreg[3465];          // (55, 63): [vt(3) | sh(30) | ex(30)]
__device__ float g_pf[BATCH * PB];      // pose feature
__device__ float g_Arel[BATCH * NJ * 12];

__constant__ int c_parents[NJ] = {
    -1, 0, 0, 0, 1, 2, 3, 4, 5, 6, 7, 8, 9, 9, 9, 12, 13, 14, 16, 17, 18, 19,
    15, 15, 15, 20, 25, 26, 20, 28, 29, 20, 31, 32, 20, 34, 35, 20, 37, 38,
    21, 40, 41, 21, 43, 44, 21, 46, 47, 21, 49, 50, 21, 52, 53};

// full_pose joint j -> source rotation matrix pointer for batch b
__device__ __forceinline__ const float* joint_R(
    int j, int b, const float* wr, const float* bp, const float* jaw,
    const float* le, const float* re, const float* lh, const float* rh)
{
    if (j == 0)  return wr + b * 9;
    if (j <= 21) return bp + (b * 21 + (j - 1)) * 9;
    if (j == 22) return jaw + b * 9;
    if (j == 23) return le + b * 9;
    if (j == 24) return re + b * 9;
    if (j <= 39) return lh + (b * 15 + (j - 25)) * 9;
    return rh + (b * 15 + (j - 40)) * 9;
}

// ---- K1: partial JR @ [vt | shapedirs | expr_dirs] per vertex chunk ----
__global__ __launch_bounds__(128) void jr_partial_kernel(
    const float* __restrict__ JR, const float* __restrict__ vt,
    const float* __restrict__ sh, const float* __restrict__ ex)
{
    __shared__ float jr_s[NJ * CHUNK];   // 55*96
    __shared__ float d_s[CHUNK * 63];    // 96*63
    int chunk = blockIdx.x;
    int v0 = chunk * CHUNK;
    int tid = threadIdx.x;

    for (int idx = tid; idx < NJ * CHUNK; idx += 128) {
        int j = idx / CHUNK, t = idx % CHUNK;
        int v = v0 + t;
        jr_s[idx] = (v < NV) ? JR[j * NV + v] : 0.f;
    }
    for (int idx = tid; idx < CHUNK * 63; idx += 128) {
        int t = idx / 63, c = idx % 63;
        int v = v0 + t;
        float val = 0.f;
        if (v < NV) {
            if (c < 3)       val = vt[v * 3 + c];
            else if (c < 33) val = sh[v * 30 + (c - 3)];
            else             val = ex[v * 30 + (c - 33)];
        }
        d_s[idx] = val;
    }
    __syncthreads();
    for (int o = tid; o < 3465; o += 128) {
        int j = o / 63, c = o % 63;
        float sum = 0.f;
        #pragma unroll 8
        for (int t = 0; t < CHUNK; t++)
            sum += jr_s[j * CHUNK + t] * d_s[t * 63 + c];
        g_jr_partial[chunk * 3465 + o] = sum;
    }
}

// ---- K2: reduce partials ----
__global__ void jr_reduce_kernel()
{
    int o = blockIdx.x * 256 + threadIdx.x;
    if (o >= 3465) return;
    float s = 0.f;
    for (int ch = 0; ch < NCH; ch++) s += g_jr_partial[ch * 3465 + o];
    g_jreg[o] = s;
}

// ---- K3: pose feature (R - I for joints 1..54) ----
__global__ void pf_kernel(
    const float* __restrict__ bp, const float* __restrict__ jaw,
    const float* __restrict__ le, const float* __restrict__ re,
    const float* __restrict__ lh, const float* __restrict__ rh)
{
    int idx = blockIdx.x * blockDim.x + threadIdx.x;
    if (idx >= BATCH * PB) return;
    int b = idx / PB, r = idx % PB;
    int j = 1 + r / 9, e = r % 9;
    const float* R = joint_R(j, b, nullptr, bp, jaw, le, re, lh, rh);
    float v = R[e] - ((e == 0 || e == 4 || e == 8) ? 1.f : 0.f);
    g_pf[idx] = v;
}

// ---- K4: per-batch joints + kinematic chain + A_rel + joints output ----
__global__ __launch_bounds__(64) void chain_kernel(
    const float* __restrict__ wr, const float* __restrict__ bp,
    const float* __restrict__ jaw, const float* __restrict__ le,
    const float* __restrict__ re, const float* __restrict__ lh,
    const float* __restrict__ rh, const float* __restrict__ shape,
    const float* __restrict__ expr, const float* __restrict__ tsl,
    float* __restrict__ out)
{
    int b = blockIdx.x;
    int tid = threadIdx.x;
    __shared__ float R_s[NJ * 9];
    __shared__ float J_s[NJ * 3];
    __shared__ float rel_s[NJ * 3];
    __shared__ float A_s[NJ * 12];

    for (int idx = tid; idx < NJ * 9; idx += 64) {
        int j = idx / 9, e = idx % 9;
        R_s[idx] = joint_R(j, b, wr, bp, jaw, le, re, lh, rh)[e];
    }
    for (int idx = tid; idx < NJ * 3; idx += 64) {
        int j = idx / 3, c = idx % 3;
        const float* base = g_jreg + j * 63;
        float v = base[c];
        #pragma unroll
        for (int k = 0; k < 10; k++) v += base[3 + c * 10 + k] * shape[b * 10 + k];
        #pragma unroll
        for (int k = 0; k < 10; k++) v += base[33 + c * 10 + k] * expr[b * 10 + k];
        J_s[idx] = v;
    }
    __syncthreads();
    for (int idx = tid; idx < NJ * 3; idx += 64) {
        int j = idx / 3, c = idx % 3;
        rel_s[idx] = J_s[idx] - ((j > 0) ? J_s[c_parents[j] * 3 + c] : 0.f);
    }
    __syncthreads();

    if (tid < 12) {
        int r = tid / 4, c = tid % 4;
        A_s[r * 4 + c] = (c < 3) ? R_s[r * 3 + c] : rel_s[r];
        __syncwarp(0x0FFF);
        for (int i = 1; i < NJ; i++) {
            int p = c_parents[i];
            const float* Ap = A_s + p * 12;
            float v;
            if (c < 3)
                v = Ap[r * 4 + 0] * R_s[i * 9 + 0 + c] +
                    Ap[r * 4 + 1] * R_s[i * 9 + 3 + c] +
                    Ap[r * 4 + 2] * R_s[i * 9 + 6 + c];
            else
                v = Ap[r * 4 + 0] * rel_s[i * 3 + 0] +
                    Ap[r * 4 + 1] * rel_s[i * 3 + 1] +
                    Ap[r * 4 + 2] * rel_s[i * 3 + 2] + Ap[r * 4 + 3];
            A_s[i * 12 + r * 4 + c] = v;
            __syncwarp(0x0FFF);
        }
    }
    __syncthreads();

    // joints output: posed + tsl
    for (int idx = tid; idx < NJ * 3; idx += 64) {
        int j = idx / 3, c = idx % 3;
        out[JOFF + b * (NJ * 3) + idx] = A_s[j * 12 + c * 4 + 3] + tsl[b * 3 + c];
    }
    // A_rel with corrected translation
    for (int idx = tid; idx < NJ * 12; idx += 64) {
        int j = idx / 12, e = idx % 12, r = e / 4, c = e % 4;
        float v;
        if (c < 3)
            v = A_s[j * 12 + r * 4 + c];
        else
            v = A_s[j * 12 + r * 4 + 3] -
                (A_s[j * 12 + r * 4 + 0] * J_s[j * 3 + 0] +
                 A_s[j * 12 + r * 4 + 1] * J_s[j * 3 + 1] +
                 A_s[j * 12 + r * 4 + 2] * J_s[j * 3 + 2]);
        g_Arel[b * (NJ * 12) + idx] = v;
    }
}

// ---- K5: fused pose-blend GEMM + shape blend + LBS skinning ----
#define BB 32   // batches per block
#define BV 64   // vertices per block
#define KC 32   // k chunk
#define JG 10   // joints per A_rel staging group

__global__ __launch_bounds__(256) void lbs_kernel(
    const float* __restrict__ posedirs, const float* __restrict__ v_template,
    const float* __restrict__ shapedirs, const float* __restrict__ expr_dirs,
    const float* __restrict__ lbsw, const float* __restrict__ body_shape,
    const float* __restrict__ expr_shape, const float* __restrict__ tsl,
    float* __restrict__ out_verts)
{
    int vt0 = blockIdx.x * BV;
    int b0 = blockIdx.y * BB;
    int tid = threadIdx.x;
    int vloc = tid & 31;
    int bg = tid >> 5;   // 0..7, 4 batches each

    __shared__ float smem[8704];
    float* pf_s = smem;            // [BB][KC]    1024
    float* pd_s = smem + 1024;     // [KC][192]   6144

    float acc[4][2][3];
    #pragma unroll
    for (int i = 0; i < 4; i++)
        #pragma unroll
        for (int s2 = 0; s2 < 2; s2++)
            #pragma unroll
            for (int c = 0; c < 3; c++) acc[i][s2][c] = 0.f;

    int col0 = vt0 * 3;
    for (int k0 = 0; k0 < PB; k0 += KC) {
        // pf tile: zero-padded past K
        #pragma unroll
        for (int it = 0; it < 4; it++) {
            int idx = it * 256 + tid;
            int bb = idx >> 5, k = idx & 31;
            float v = 0.f;
            if (k0 + k < PB) v = g_pf[(b0 + bb) * PB + k0 + k];
            pf_s[bb * KC + k] = v;
        }
        // pd tile
        #pragma unroll
        for (int it = 0; it < 24; it++) {
            int idx = it * 256 + tid;
            int k = idx / 192, col = idx % 192;
            int gc = col0 + col;
            float v = 0.f;
            if (k0 + k < PB && gc < NC3) v = posedirs[(k0 + k) * NC3 + gc];
            pd_s[k * 192 + col] = v;
        }
        __syncthreads();
        #pragma unroll 8
        for (int k = 0; k < KC; k++) {
            float a[4], p[2][3];
            #pragma unroll
            for (int i = 0; i < 4; i++) a[i] = pf_s[(bg * 4 + i) * KC + k];
            #pragma unroll
            for (int s2 = 0; s2 < 2; s2++)
                #pragma unroll
                for (int c = 0; c < 3; c++)
                    p[s2][c] = pd_s[k * 192 + (vloc + 32 * s2) * 3 + c];
            #pragma unroll
            for (int i = 0; i < 4; i++)
                #pragma unroll
                for (int s2 = 0; s2 < 2; s2++)
                    #pragma unroll
                    for (int c = 0; c < 3; c++)
                        acc[i][s2][c] += a[i] * p[s2][c];
        }
        __syncthreads();
    }

    // ---- epilogue: re-stage smem ----
    float* sh_s  = smem;           // [64][30] 1920   (dead after vp computed)
    float* ex_s  = smem + 1920;    // 1920            (dead after vp computed)
    float* vt_s  = smem + 3840;    // [64][3]  192    (dead after vp computed)
    float* w_s   = smem + 4032;    // [64][55] 3520   (live through j-loop)
    float* be_s  = smem + 7552;    // [32][10] 320    (dead after vp)
    float* exb_s = smem + 7872;    // 320             (dead after vp)
    float* ts_s  = smem + 8192;    // [32][3]  96     (live to the end)

    for (int idx = tid; idx < 1920; idx += 256) {
        int v = idx / 30, e = idx % 30;
        int gv = vt0 + v;
        sh_s[idx] = (gv < NV) ? shapedirs[gv * 30 + e] : 0.f;
        ex_s[idx] = (gv < NV) ? expr_dirs[gv * 30 + e] : 0.f;
    }
    for (int idx = tid; idx < 192; idx += 256) {
        int v = idx / 3, c = idx % 3;
        int gv = vt0 + v;
        vt_s[idx] = (gv < NV) ? v_template[gv * 3 + c] : 0.f;
    }
    for (int idx = tid; idx < 3520; idx += 256) {
        int v = idx / 55, j = idx % 55;
        int gv = vt0 + v;
        w_s[idx] = (gv < NV) ? lbsw[gv * 55 + j] : 0.f;
    }
    for (int idx = tid; idx < 320; idx += 256) {
        int bb = idx / 10, k = idx % 10;
        be_s[idx]  = body_shape[(b0 + bb) * 10 + k];
        exb_s[idx] = expr_shape[(b0 + bb) * 10 + k];
    }
    for (int idx = tid; idx < 96; idx += 256)
        ts_s[idx] = tsl[b0 * 3 + idx];
    __syncthreads();

    // v_posed = pose-correction + v_template + shape blend + expr blend
    float vp[4][2][3];
    #pragma unroll
    for (int i = 0; i < 4; i++) {
        int bl = bg * 4 + i;
        #pragma unroll
        for (int s2 = 0; s2 < 2; s2++) {
            int vl = vloc + 32 * s2;
            #pragma unroll
            for (int c = 0; c < 3; c++) {
                float v = acc[i][s2][c] + vt_s[vl * 3 + c];
                #pragma unroll
                for (int k = 0; k < 10; k++)
                    v += sh_s[vl * 30 + c * 10 + k] * be_s[bl * 10 + k];
                #pragma unroll
                for (int k = 0; k < 10; k++)
                    v += ex_s[vl * 30 + c * 10 + k] * exb_s[bl * 10 + k];
                vp[i][s2][c] = v;
            }
        }
    }

    float o[4][2][3];
    #pragma unroll
    for (int i = 0; i < 4; i++)
        #pragma unroll
        for (int s2 = 0; s2 < 2; s2++)
            #pragma unroll
            for (int c = 0; c < 3; c++) o[i][s2][c] = 0.f;

    // Skinning: stage A_rel in groups of JG joints into the (now dead)
    // sh_s region. [32 batches][JG joints][12] = 3840 floats max.
    float* arg_s = smem;  // overlaps sh_s/ex_s/vt_s — dead after vp
    for (int j0 = 0; j0 < NJ; j0 += JG) {
        int njg = (NJ - j0 < JG) ? (NJ - j0) : JG;
        __syncthreads();   // protect prior reads of arg_s region (incl. vp stage)
        for (int idx = tid; idx < BB * njg * 12; idx += 256) {
            int bb = idx / (njg * 12);
            int rem = idx % (njg * 12);
            arg_s[bb * (JG * 12) + rem] =
                g_Arel[(b0 + bb) * (NJ * 12) + (j0 * 12) + rem];
        }
        __syncthreads();
        for (int jj = 0; jj < njg; jj++) {
            int j = j0 + jj;
            #pragma unroll
            for (int i = 0; i < 4; i++) {
                int bl = bg * 4 + i;
                float m[12];
                #pragma unroll
                for (int e = 0; e < 12; e++)
                    m[e] = arg_s[bl * (JG * 12) + jj * 12 + e];
                #pragma unroll
                for (int s2 = 0; s2 < 2; s2++) {
                    float w = w_s[(vloc + 32 * s2) * 55 + j];
                    float x = vp[i][s2][0], y = vp[i][s2][1], z = vp[i][s2][2];
                    o[i][s2][0] += w * (m[0] * x + m[1] * y + m[2]  * z + m[3]);
                    o[i][s2][1] += w * (m[4] * x + m[5] * y + m[6]  * z + m[7]);
                    o[i][s2][2] += w * (m[8] * x + m[9] * y + m[10] * z + m[11]);
                }
            }
        }
    }

    #pragma unroll
    for (int i = 0; i < 4; i++) {
        int bl = bg * 4 + i;
        int b = b0 + bl;
        #pragma unroll
        for (int s2 = 0; s2 < 2; s2++) {
            int v = vt0 + vloc + 32 * s2;
            if (v < NV) {
                #pragma unroll
                for (int c = 0; c < 3; c++)
                    out_verts[b * NC3 + v * 3 + c] = o[i][s2][c] + ts_s[bl * 3 + c];
            }
        }
    }
}

extern "C" void kernel_launch(void* const* d_in, const int* in_sizes, int n_in,
                              void* d_out, int out_size)
{
    const float* world_rot  = (const float*)d_in[0];
    const float* world_tsl  = (const float*)d_in[1];
    const float* body_shape = (const float*)d_in[2];
    const float* body_pose  = (const float*)d_in[3];
    const float* lhand      = (const float*)d_in[4];
    const float* rhand      = (const float*)d_in[5];
    const float* expr_shape = (const float*)d_in[6];
    const float* jaw        = (const float*)d_in[7];
    const float* leye       = (const float*)d_in[8];
    const float* reye       = (const float*)d_in[9];
    const float* v_template = (const float*)d_in[10];
    const float* shapedirs  = (const float*)d_in[11];
    const float* expr_dirs  = (const float*)d_in[12];
    const float* posedirs   = (const float*)d_in[13];
    const float* J_reg      = (const float*)d_in[14];
    const float* lbsw       = (const float*)d_in[15];
    float* out = (float*)d_out;

    jr_partial_kernel<<<NCH, 128>>>(J_reg, v_template, shapedirs, expr_dirs);
    jr_reduce_kernel<<<(3465 + 255) / 256, 256>>>();
    pf_kernel<<<(BATCH * PB + 255) / 256, 256>>>(body_pose, jaw, leye, reye, lhand, rhand);
    chain_kernel<<<BATCH, 64>>>(world_rot, body_pose, jaw, leye, reye, lhand,
                                rhand, body_shape, expr_shape, world_tsl, out);
    dim3 grid((NV + BV - 1) / BV, BATCH / BB);
    lbs_kernel<<<grid, 256>>>(posedirs, v_template, shapedirs, expr_dirs,
                              lbsw, body_shape, expr_shape, world_tsl, out);
}